// round 15
// baseline (speedup 1.0000x reference)
#include <cuda_runtime.h>
#include <math.h>

// ---------------- problem constants ----------------
#define BATCH   32
#define NN      96          // N_NODES == LATENT
#define H1D     512
#define H2D     1024
#define LDEC    4
#define NSQ     9216        // 96*96

// d_out layout: x_output[32*9216], y_output[32], z[32*96], log_q[32*96]
#define X_OFF   0
#define Y_OFF   294912
#define Z_OFF   294944
#define LQ_OFF  298016

#define KS1     36          // split-K for enc1
#define KS2     16          // split-K for enc2

// ---- fc GEMM config (bf16 mma m16n8k16, cp.async W): 256 cols/block, split-K 4 ----
#define FCBN    256             // cols per block
#define FCBK    64              // k per tile
#define FCKS    4               // k splits
#define FCKCH   (NSQ / FCKS)    // 2304
#define FCTILES (FCKCH / FCBK)  // 36
#define FCNB    (NSQ / FCBN)    // 36 n-blocks
#define WS_F    72              // W smem stride in f32 words (conflict-free LDS.64)
#define ASB_STRIDE 36           // A smem row stride in bf16x2 words
#define WSF_WORDS (FCBN * WS_F)          // 18432
#define ASB_WORDS (BATCH * ASB_STRIDE)   // 1152
#define FC_SMEM_BYTES ((2 * WSF_WORDS + 2 * ASB_WORDS) * 4)   // 156672

// ---------------- device scratch ----------------
__device__ float g_part1[KS1 * BATCH * H2D];
__device__ float g_h1  [BATCH * H2D];
__device__ float g_part2[KS2 * BATCH * H1D];
__device__ float g_h2  [BATCH * H1D];
__device__ float g_mu  [BATCH * NN];
__device__ float g_lv  [BATCH * NN];
__device__ float g_z   [BATCH * NN];
__device__ float g_d   [LDEC * BATCH * NN];
__device__ float g_gg  [LDEC * BATCH * NN];
__device__ float g_pre [BATCH * NSQ];
__device__ float g_pfc [FCKS * BATCH * NSQ];
__device__ int   g_fc_cnt[FCNB];

// ---------------- threefry2x32 (JAX, key=42, partitionable: out0^out1) ----------------
#define TF_ROUND(x0, x1, r) do { x0 += x1; x1 = (x1 << (r)) | (x1 >> (32 - (r))); x1 ^= x0; } while (0)

__device__ __forceinline__ float tf_normal(int i) {
    const unsigned ks0 = 0u, ks1 = 42u;
    const unsigned ks2 = 0x1BD11BDAu ^ ks0 ^ ks1;
    unsigned x0 = 0u + ks0;
    unsigned x1 = (unsigned)i + ks1;
    TF_ROUND(x0,x1,13); TF_ROUND(x0,x1,15); TF_ROUND(x0,x1,26); TF_ROUND(x0,x1,6);
    x0 += ks1; x1 += ks2 + 1u;
    TF_ROUND(x0,x1,17); TF_ROUND(x0,x1,29); TF_ROUND(x0,x1,16); TF_ROUND(x0,x1,24);
    x0 += ks2; x1 += ks0 + 2u;
    TF_ROUND(x0,x1,13); TF_ROUND(x0,x1,15); TF_ROUND(x0,x1,26); TF_ROUND(x0,x1,6);
    x0 += ks0; x1 += ks1 + 3u;
    TF_ROUND(x0,x1,17); TF_ROUND(x0,x1,29); TF_ROUND(x0,x1,16); TF_ROUND(x0,x1,24);
    x0 += ks1; x1 += ks2 + 4u;
    TF_ROUND(x0,x1,13); TF_ROUND(x0,x1,15); TF_ROUND(x0,x1,26); TF_ROUND(x0,x1,6);
    x0 += ks2; x1 += ks0 + 5u;
    unsigned b = x0 ^ x1;
    float u = __uint_as_float(0x3F800000u | (b >> 9)) - 1.0f;
    const float lo = __uint_as_float(0xBF7FFFFFu);
    float v = fmaxf(u * 2.0f + lo, lo);
    return 1.41421354f * erfinvf(v);
}

// ---------------- encoder split-K GEMM ----------------
__global__ void gemm_tn_splitk(const float* __restrict__ A, const float* __restrict__ W,
                               float* __restrict__ part, int N, int K, int kchunk)
{
    const int BN = 64, BK = 32;
    const int n0 = blockIdx.x * BN;
    const int s  = blockIdx.y;
    const int kb = s * kchunk;
    const int ke = kb + kchunk;

    __shared__ __align__(16) float As[32][36];
    __shared__ __align__(16) float Ws[32][66];

    const int tid = threadIdx.x;
    const int cx  = tid & 31;
    const int by  = tid >> 5;
    const int kk  = tid & 31;
    const int rr  = tid >> 5;

    float acc[4][2] = {};

    for (int k0 = kb; k0 < ke; k0 += BK) {
        __syncthreads();
        #pragma unroll
        for (int i = 0; i < 4; i++)
            As[kk][rr + 8*i] = A[(rr + 8*i) * K + k0 + kk];
        #pragma unroll
        for (int i = 0; i < BN/8; i++)
            Ws[kk][rr + 8*i] = W[(size_t)(n0 + rr + 8*i) * K + k0 + kk];
        __syncthreads();
        #pragma unroll
        for (int t = 0; t < BK; t++) {
            float4 a = *(const float4*)&As[t][4*by];
            float2 w = *(const float2*)&Ws[t][2*cx];
            acc[0][0] = fmaf(a.x, w.x, acc[0][0]);
            acc[0][1] = fmaf(a.x, w.y, acc[0][1]);
            acc[1][0] = fmaf(a.y, w.x, acc[1][0]);
            acc[1][1] = fmaf(a.y, w.y, acc[1][1]);
            acc[2][0] = fmaf(a.z, w.x, acc[2][0]);
            acc[2][1] = fmaf(a.z, w.y, acc[2][1]);
            acc[3][0] = fmaf(a.w, w.x, acc[3][0]);
            acc[3][1] = fmaf(a.w, w.y, acc[3][1]);
        }
    }
    #pragma unroll
    for (int i = 0; i < 4; i++)
        #pragma unroll
        for (int j = 0; j < 2; j++)
            part[((size_t)s * BATCH + 4*by + i) * N + n0 + 2*cx + j] = acc[i][j];
}

// templated S -> fully unrolled partial reduction
template<int S, bool RELU>
__global__ void reduce_act_t(const float* __restrict__ part,
                             const float* __restrict__ bias,
                             float* __restrict__ out, int N)
{
    int idx = blockIdx.x * 256 + threadIdx.x;
    if (idx >= BATCH * N) return;
    int n = idx % N;
    float a = bias[n];
    #pragma unroll
    for (int s = 0; s < S; s++) a += part[(size_t)s * BATCH * N + idx];
    out[idx] = RELU ? fmaxf(a, 0.0f) : a;
}

// ---------------- group-conditioned mu/logvar heads (6144 warp dots) ----------------
__global__ void heads_kernel(const float* __restrict__ h2, const float* __restrict__ c,
                             const float* __restrict__ mu0w, const float* __restrict__ mu0b,
                             const float* __restrict__ lv0w, const float* __restrict__ lv0b,
                             const float* __restrict__ mu1w, const float* __restrict__ mu1b,
                             const float* __restrict__ lv1w, const float* __restrict__ lv1b,
                             float* __restrict__ mu, float* __restrict__ lv)
{
    int w = blockIdx.x * (blockDim.x >> 5) + (threadIdx.x >> 5);
    int lane = threadIdx.x & 31;
    if (w >= BATCH * 2 * NN) return;
    int b = w / (2 * NN);
    int r = w % (2 * NN);
    int which = r / NN;
    int n = r % NN;
    bool is0 = (c[b] == 0.0f);
    const float* wp = which == 0 ? (is0 ? mu0w : mu1w) : (is0 ? lv0w : lv1w);
    const float* bp = which == 0 ? (is0 ? mu0b : mu1b) : (is0 ? lv0b : lv1b);
    const float* hr = h2 + b * H1D;
    const float* wr = wp + n * H1D;
    float acc = 0.0f;
    #pragma unroll 4
    for (int k = lane; k < H1D; k += 32) acc = fmaf(hr[k], wr[k], acc);
    #pragma unroll
    for (int o = 16; o; o >>= 1) acc += __shfl_xor_sync(0xFFFFFFFFu, acc, o);
    if (lane == 0) (which ? lv : mu)[b * NN + n] = acc + bp[n];
}

// ---------------- fused reparam (inline eps) + z/log_q + y (one block per batch) ---------
__global__ void reparam_y_kernel(const float* __restrict__ mu, const float* __restrict__ lv,
                                 const float* __restrict__ c,
                                 const float* __restrict__ reg_w, const float* __restrict__ reg_b,
                                 float* __restrict__ z_scr, float* __restrict__ out)
{
    const int b = blockIdx.x;
    const int n = threadIdx.x;      // 96 threads
    const int lane = n & 31;
    __shared__ float zs[NN];

    float m = mu[b*NN + n], v = lv[b*NN + n];
    float e = tf_normal(b*NN + n);
    float sd = expf(0.5f * v);
    float z = fmaf(e, sd, m);
    zs[n] = z;
    z_scr[b*NN + n] = z;
    out[Z_OFF  + b*NN + n] = z;
    out[LQ_OFF + b*NN + n] = fmaf(-0.5f * e, e, -0.5f * v) - 0.91893853320467274f;
    __syncthreads();

    if (n < 32) {
        float s = 0.0f;
        #pragma unroll
        for (int l = lane; l < NN; l += 32) s = fmaf(zs[l], reg_w[l], s);
        #pragma unroll
        for (int o = 16; o; o >>= 1) s += __shfl_xor_sync(0xFFFFFFFFu, s, o);
        if (lane == 0) out[Y_OFF + b] = s + c[b] * reg_w[NN] + reg_b[0];
    }
}

// ---------------- fused decoder + graphconv (same 128-block grid as before) --------------
__global__ void dec_gc_kernel(const float* __restrict__ z, const float* __restrict__ c,
                              const float* __restrict__ dec_w, const float* __restrict__ dec_b,
                              const float* __restrict__ gc0w, const float* __restrict__ gc0b,
                              const float* __restrict__ gc1w, const float* __restrict__ gc1b,
                              float* __restrict__ g)
{
    int k = blockIdx.x, b = blockIdx.y, n = threadIdx.x;   // 96 threads
    __shared__ float zs[NN];
    __shared__ float ds[NN];
    zs[n] = z[b*NN + n];
    __syncthreads();

    // decoder
    {
        const float* wr = dec_w + (k*NN + n) * NN;
        float acc = dec_b[k*NN + n];
        #pragma unroll 8
        for (int l = 0; l < NN; l++) acc = fmaf(zs[l], wr[l], acc);
        ds[n] = 1.0f / (1.0f + expf(-acc));
    }
    __syncthreads();

    // graphconv (group-selected)
    bool is0 = (c[b] == 0.0f);
    const float* wr = (is0 ? gc0w : gc1w) + (k*NN + n) * NN;
    const float* bp = is0 ? gc0b : gc1b;
    float acc = bp[k*NN + n];
    #pragma unroll 8
    for (int l = 0; l < NN; l++) acc = fmaf(ds[l], wr[l], acc);
    g[(k*BATCH + b)*NN + n] = 1.0f / (1.0f + expf(-acc));
}

// ---------------- pre[b, i*96+j] = b_sel + sum_k W_sel[k] g[k,b,i] g[k,b,j] ----------------
__global__ void outer_kernel(const float* __restrict__ g, const float* __restrict__ c,
                             const float* __restrict__ W0, const float* __restrict__ b0v,
                             const float* __restrict__ W1, const float* __restrict__ b1v,
                             float* __restrict__ pre)
{
    int b = blockIdx.x, tid = threadIdx.x;
    __shared__ float gi[LDEC][NN];
    __shared__ float wg[LDEC][NN];
    bool is0 = (c[b] == 0.0f);
    const float* Wsel = is0 ? W0 : W1;
    const float* bsel = is0 ? b0v : b1v;
    for (int idx = tid; idx < LDEC * NN; idx += 256) {
        int k = idx / NN, n = idx % NN;
        float gv = g[(k*BATCH + b)*NN + n];
        gi[k][n] = gv;
        wg[k][n] = gv * Wsel[k];
    }
    __syncthreads();
    for (int idx = tid; idx < NSQ; idx += 256) {
        int i = idx / NN, j = idx % NN;
        float v = bsel[idx];
        #pragma unroll
        for (int k = 0; k < LDEC; k++) v = fmaf(wg[k][i], gi[k][j], v);
        pre[(size_t)b * NSQ + idx] = v;
    }
}

// ---------------- big fc GEMM: bf16 mma, cp.async W, split-K, fused combine/exp ----------
__device__ __forceinline__ unsigned pack_bf16(float lo, float hi) {
    unsigned r;
    asm("cvt.rn.bf16x2.f32 %0, %1, %2;" : "=r"(r) : "f"(hi), "f"(lo));
    return r;
}

__device__ __forceinline__ void cp16(void* smem_dst, const void* gsrc) {
    unsigned s = (unsigned)__cvta_generic_to_shared(smem_dst);
    asm volatile("cp.async.ca.shared.global [%0], [%1], 16;" :: "r"(s), "l"(gsrc));
}
#define CP_COMMIT() asm volatile("cp.async.commit_group;")
#define CP_WAIT(n)  asm volatile("cp.async.wait_group %0;" :: "n"(n))

#define MMA_BF16(d, a, b0, b1) \
    asm volatile("mma.sync.aligned.m16n8k16.row.col.f32.bf16.bf16.f32 " \
                 "{%0,%1,%2,%3}, {%4,%5,%6,%7}, {%8,%9}, {%0,%1,%2,%3};" \
                 : "+f"(d[0]), "+f"(d[1]), "+f"(d[2]), "+f"(d[3]) \
                 : "r"(a[0]), "r"(a[1]), "r"(a[2]), "r"(a[3]), "r"(b0), "r"(b1))

__global__ void __launch_bounds__(256, 1)
gemm_fc_mma(const float* __restrict__ A, const float* __restrict__ W,
            const float* __restrict__ bias,
            float* __restrict__ part, int* __restrict__ cnt,
            float* __restrict__ xout)
{
    extern __shared__ float sm[];
    float*    WsBuf0 = sm;
    float*    WsBuf1 = sm + WSF_WORDS;
    unsigned* AsBuf0 = (unsigned*)(sm + 2*WSF_WORDS);
    unsigned* AsBuf1 = AsBuf0 + ASB_WORDS;

    const int tid  = threadIdx.x;
    const int lane = tid & 31;
    const int wid  = tid >> 5;
    const int q    = lane >> 2;
    const int s    = lane & 3;
    const int n0   = blockIdx.x * FCBN;
    const int kb   = blockIdx.y * FCKCH;

    float4 ast[2];
    float acc[2][4][4];
    #pragma unroll
    for (int rt = 0; rt < 2; rt++)
        #pragma unroll
        for (int j = 0; j < 4; j++)
            #pragma unroll
            for (int cc = 0; cc < 4; cc++) acc[rt][j][cc] = 0.0f;

    auto cp_w = [&](float* ws, int kt) {
        const float* wb = W + (size_t)kb + (size_t)kt * FCBK;
        #pragma unroll
        for (int it = 0; it < 16; it++) {
            int idx = it*256 + tid;
            int ci = idx >> 4, k4 = idx & 15;
            cp16(ws + ci * WS_F + 4*k4, wb + (size_t)(n0 + ci) * NSQ + 4*k4);
        }
    };
    auto lda = [&](int kt) {
        const float* ab = A + (size_t)lane * NSQ + kb + kt * FCBK;
        #pragma unroll
        for (int it = 0; it < 2; it++) ast[it] = *(const float4*)(ab + 4*(8*it + wid));
    };
    auto sta = [&](unsigned* as) {
        #pragma unroll
        for (int it = 0; it < 2; it++) {
            int k4 = 8*it + wid;
            as[lane * ASB_STRIDE + 2*k4]     = pack_bf16(ast[it].x, ast[it].y);
            as[lane * ASB_STRIDE + 2*k4 + 1] = pack_bf16(ast[it].z, ast[it].w);
        }
    };

    auto compute_tile = [&](const float* Wf, const unsigned* As) {
        #pragma unroll
        for (int k16 = 0; k16 < FCBK/16; k16++) {
            int koff = 8*k16;
            int ko   = 16*k16;
            unsigned a[2][4];
            #pragma unroll
            for (int rt = 0; rt < 2; rt++) {
                int r0 = q + 16*rt;
                a[rt][0] = As[r0 * ASB_STRIDE + s + koff];
                a[rt][1] = As[(r0 + 8) * ASB_STRIDE + s + koff];
                a[rt][2] = As[r0 * ASB_STRIDE + s + 4 + koff];
                a[rt][3] = As[(r0 + 8) * ASB_STRIDE + s + 4 + koff];
            }
            #pragma unroll
            for (int j = 0; j < 4; j++) {
                int ci = wid*32 + j*8 + q;
                const float* wp = Wf + ci * WS_F + ko;
                float2 w0 = *(const float2*)(wp + 2*s);
                float2 w1 = *(const float2*)(wp + 2*s + 8);
                unsigned b0 = pack_bf16(w0.x, w0.y);
                unsigned b1 = pack_bf16(w1.x, w1.y);
                MMA_BF16(acc[0][j], a[0], b0, b1);
                MMA_BF16(acc[1][j], a[1], b0, b1);
            }
        }
    };

    cp_w(WsBuf0, 0); CP_COMMIT();
    lda(0); sta(AsBuf0);
    cp_w(WsBuf1, 1); CP_COMMIT();
    lda(1);
    CP_WAIT(1);
    __syncthreads();

    for (int t = 0; t < FCTILES; t++) {
        const int p = t & 1;
        compute_tile(p ? WsBuf1 : WsBuf0, p ? AsBuf1 : AsBuf0);
        if (t + 1 < FCTILES) {
            sta(p ? AsBuf0 : AsBuf1);
            CP_WAIT(0);
            __syncthreads();
            if (t + 2 < FCTILES) {
                cp_w(p ? WsBuf1 : WsBuf0, t + 2);
                CP_COMMIT();
                lda(t + 2);
            }
        }
    }

    // write partials
    float* pbase = part + (size_t)blockIdx.y * BATCH * NSQ;
    #pragma unroll
    for (int rt = 0; rt < 2; rt++) {
        #pragma unroll
        for (int j = 0; j < 4; j++) {
            int row = q + 16*rt;
            int col = n0 + wid*32 + j*8 + 2*s;
            *(float2*)&pbase[(size_t)row * NSQ + col] =
                make_float2(acc[rt][j][0], acc[rt][j][1]);
            *(float2*)&pbase[(size_t)(row + 8) * NSQ + col] =
                make_float2(acc[rt][j][2], acc[rt][j][3]);
        }
    }

    // last-block-per-n-slab combines partials + bias, applies exp (threadfence reduction)
    __threadfence();
    __shared__ int ticket;
    if (tid == 0) ticket = atomicAdd(&cnt[blockIdx.x], 1);
    __syncthreads();
    if (ticket == FCKS - 1) {
        for (int idx = tid; idx < BATCH * FCBN; idx += 256) {
            int b = idx >> 8;              // /FCBN
            int cc = idx & (FCBN - 1);
            size_t off = (size_t)b * NSQ + n0 + cc;
            float a = bias[n0 + cc];
            #pragma unroll
            for (int sp = 0; sp < FCKS; sp++)
                a += __ldcg(part + (size_t)sp * BATCH * NSQ + off);
            xout[off] = expf(a);
        }
    }
}

// ---------------- launch ----------------
extern "C" void kernel_launch(void* const* d_in, const int* in_sizes, int n_in,
                              void* d_out, int out_size)
{
    const float* x_in   = (const float*)d_in[0];
    const float* c_in   = (const float*)d_in[1];
    const float* enc_w1 = (const float*)d_in[2];
    const float* enc_b1 = (const float*)d_in[3];
    const float* enc_w2 = (const float*)d_in[4];
    const float* enc_b2 = (const float*)d_in[5];
    const float* mu0_w  = (const float*)d_in[6];
    const float* mu0_b  = (const float*)d_in[7];
    const float* lv0_w  = (const float*)d_in[8];
    const float* lv0_b  = (const float*)d_in[9];
    const float* mu1_w  = (const float*)d_in[10];
    const float* mu1_b  = (const float*)d_in[11];
    const float* lv1_w  = (const float*)d_in[12];
    const float* lv1_b  = (const float*)d_in[13];
    const float* dec_w  = (const float*)d_in[14];
    const float* dec_b  = (const float*)d_in[15];
    const float* gc0_w  = (const float*)d_in[16];
    const float* gc0_b  = (const float*)d_in[17];
    const float* gc1_w  = (const float*)d_in[18];
    const float* gc1_b  = (const float*)d_in[19];
    const float* fc_w   = (const float*)d_in[20];
    const float* fc_b   = (const float*)d_in[21];
    const float* reg_w  = (const float*)d_in[22];
    const float* reg_b  = (const float*)d_in[23];
    const float* W0     = (const float*)d_in[24];
    const float* b0v    = (const float*)d_in[25];
    const float* W1     = (const float*)d_in[26];
    const float* b1v    = (const float*)d_in[27];
    float* out = (float*)d_out;

    void *p;
    float *part1, *h1, *part2, *h2, *mu, *lv, *z, *gbuf, *pre, *pfc;
    int *cnt;
    cudaGetSymbolAddress(&p, g_part1);  part1 = (float*)p;
    cudaGetSymbolAddress(&p, g_h1);     h1    = (float*)p;
    cudaGetSymbolAddress(&p, g_part2);  part2 = (float*)p;
    cudaGetSymbolAddress(&p, g_h2);     h2    = (float*)p;
    cudaGetSymbolAddress(&p, g_mu);     mu    = (float*)p;
    cudaGetSymbolAddress(&p, g_lv);     lv    = (float*)p;
    cudaGetSymbolAddress(&p, g_z);      z     = (float*)p;
    cudaGetSymbolAddress(&p, g_gg);     gbuf  = (float*)p;
    cudaGetSymbolAddress(&p, g_pre);    pre   = (float*)p;
    cudaGetSymbolAddress(&p, g_pfc);    pfc   = (float*)p;
    cudaGetSymbolAddress(&p, g_fc_cnt); cnt   = (int*)p;

    cudaFuncSetAttribute(gemm_fc_mma, cudaFuncAttributeMaxDynamicSharedMemorySize,
                         FC_SMEM_BYTES);

    // zero the fc completion counters (graph-capturable)
    cudaMemsetAsync(cnt, 0, FCNB * sizeof(int));

    // encoder
    gemm_tn_splitk<<<dim3(H2D/64, KS1), 256>>>(x_in, enc_w1, part1, H2D, NSQ, NSQ/KS1);
    reduce_act_t<KS1, true><<<(BATCH*H2D + 255)/256, 256>>>(part1, enc_b1, h1, H2D);
    gemm_tn_splitk<<<dim3(H1D/64, KS2), 256>>>(h1, enc_w2, part2, H1D, H2D, H2D/KS2);
    reduce_act_t<KS2, true><<<(BATCH*H1D + 255)/256, 256>>>(part2, enc_b2, h2, H1D);

    // heads (wide parallelism: 6144 warp dots)
    heads_kernel<<<768, 256>>>(h2, c_in, mu0_w, mu0_b, lv0_w, lv0_b,
                               mu1_w, mu1_b, lv1_w, lv1_b, mu, lv);

    // fused reparam + z/log_q + y
    reparam_y_kernel<<<BATCH, NN>>>(mu, lv, c_in, reg_w, reg_b, z, out);

    // fused decoder + graphconv (128 blocks)
    dec_gc_kernel<<<dim3(LDEC, BATCH), NN>>>(z, c_in, dec_w, dec_b,
                                             gc0_w, gc0_b, gc1_w, gc1_b, gbuf);
    outer_kernel<<<BATCH, 256>>>(gbuf, c_in, W0, b0v, W1, b1v, pre);

    // fc GEMM (bf16 tensor cores, cp.async W, split-K) with fused combine/exp epilogue
    gemm_fc_mma<<<dim3(FCNB, FCKS), 256, FC_SMEM_BYTES>>>(pre, fc_w, fc_b, pfc, cnt,
                                                          out + X_OFF);
}

// round 17
// speedup vs baseline: 1.1002x; 1.1002x over previous
#include <cuda_runtime.h>
#include <math.h>

// ---------------- problem constants ----------------
#define BATCH   32
#define NN      96          // N_NODES == LATENT
#define H1D     512
#define H2D     1024
#define LDEC    4
#define NSQ     9216        // 96*96

// d_out layout: x_output[32*9216], y_output[32], z[32*96], log_q[32*96]
#define X_OFF   0
#define Y_OFF   294912
#define Z_OFF   294944
#define LQ_OFF  298016

#define KS1     36          // split-K for enc1
#define KS2     16          // split-K for enc2

// ---- fc GEMM config (bf16 mma m16n8k16, cp.async W): 256 cols/block, split-K 4 ----
#define FCBN    256             // cols per block
#define FCBK    64              // k per tile
#define FCKS    4               // k splits
#define FCKCH   (NSQ / FCKS)    // 2304
#define FCTILES (FCKCH / FCBK)  // 36
#define WS_F    72              // W smem stride in f32 words (conflict-free LDS.64)
#define ASB_STRIDE 36           // A smem row stride in bf16x2 words
#define WSF_WORDS (FCBN * WS_F)          // 18432
#define ASB_WORDS (BATCH * ASB_STRIDE)   // 1152
#define FC_SMEM_BYTES ((2 * WSF_WORDS + 2 * ASB_WORDS) * 4)   // 156672

// ---------------- device scratch ----------------
__device__ float g_part1[KS1 * BATCH * H2D];
__device__ float g_h1  [BATCH * H2D];
__device__ float g_part2[KS2 * BATCH * H1D];
__device__ float g_h2  [BATCH * H1D];
__device__ float g_mu  [BATCH * NN];
__device__ float g_lv  [BATCH * NN];
__device__ float g_z   [BATCH * NN];
__device__ float g_gg  [LDEC * BATCH * NN];
__device__ float g_pre [BATCH * NSQ];
__device__ float g_pfc [FCKS * BATCH * NSQ];

// ---------------- threefry2x32 (JAX, key=42, partitionable: out0^out1) ----------------
#define TF_ROUND(x0, x1, r) do { x0 += x1; x1 = (x1 << (r)) | (x1 >> (32 - (r))); x1 ^= x0; } while (0)

__device__ __forceinline__ float tf_normal(int i) {
    const unsigned ks0 = 0u, ks1 = 42u;
    const unsigned ks2 = 0x1BD11BDAu ^ ks0 ^ ks1;
    unsigned x0 = 0u + ks0;
    unsigned x1 = (unsigned)i + ks1;
    TF_ROUND(x0,x1,13); TF_ROUND(x0,x1,15); TF_ROUND(x0,x1,26); TF_ROUND(x0,x1,6);
    x0 += ks1; x1 += ks2 + 1u;
    TF_ROUND(x0,x1,17); TF_ROUND(x0,x1,29); TF_ROUND(x0,x1,16); TF_ROUND(x0,x1,24);
    x0 += ks2; x1 += ks0 + 2u;
    TF_ROUND(x0,x1,13); TF_ROUND(x0,x1,15); TF_ROUND(x0,x1,26); TF_ROUND(x0,x1,6);
    x0 += ks0; x1 += ks1 + 3u;
    TF_ROUND(x0,x1,17); TF_ROUND(x0,x1,29); TF_ROUND(x0,x1,16); TF_ROUND(x0,x1,24);
    x0 += ks1; x1 += ks2 + 4u;
    TF_ROUND(x0,x1,13); TF_ROUND(x0,x1,15); TF_ROUND(x0,x1,26); TF_ROUND(x0,x1,6);
    x0 += ks2; x1 += ks0 + 5u;
    unsigned b = x0 ^ x1;
    float u = __uint_as_float(0x3F800000u | (b >> 9)) - 1.0f;
    const float lo = __uint_as_float(0xBF7FFFFFu);
    float v = fmaxf(u * 2.0f + lo, lo);
    return 1.41421354f * erfinvf(v);
}

// ---------------- encoder split-K GEMM ----------------
__global__ void gemm_tn_splitk(const float* __restrict__ A, const float* __restrict__ W,
                               float* __restrict__ part, int N, int K, int kchunk)
{
    const int BN = 64, BK = 32;
    const int n0 = blockIdx.x * BN;
    const int s  = blockIdx.y;
    const int kb = s * kchunk;
    const int ke = kb + kchunk;

    __shared__ __align__(16) float As[32][36];
    __shared__ __align__(16) float Ws[32][66];

    const int tid = threadIdx.x;
    const int cx  = tid & 31;
    const int by  = tid >> 5;
    const int kk  = tid & 31;
    const int rr  = tid >> 5;

    float acc[4][2] = {};

    for (int k0 = kb; k0 < ke; k0 += BK) {
        __syncthreads();
        #pragma unroll
        for (int i = 0; i < 4; i++)
            As[kk][rr + 8*i] = A[(rr + 8*i) * K + k0 + kk];
        #pragma unroll
        for (int i = 0; i < BN/8; i++)
            Ws[kk][rr + 8*i] = W[(size_t)(n0 + rr + 8*i) * K + k0 + kk];
        __syncthreads();
        #pragma unroll
        for (int t = 0; t < BK; t++) {
            float4 a = *(const float4*)&As[t][4*by];
            float2 w = *(const float2*)&Ws[t][2*cx];
            acc[0][0] = fmaf(a.x, w.x, acc[0][0]);
            acc[0][1] = fmaf(a.x, w.y, acc[0][1]);
            acc[1][0] = fmaf(a.y, w.x, acc[1][0]);
            acc[1][1] = fmaf(a.y, w.y, acc[1][1]);
            acc[2][0] = fmaf(a.z, w.x, acc[2][0]);
            acc[2][1] = fmaf(a.z, w.y, acc[2][1]);
            acc[3][0] = fmaf(a.w, w.x, acc[3][0]);
            acc[3][1] = fmaf(a.w, w.y, acc[3][1]);
        }
    }
    #pragma unroll
    for (int i = 0; i < 4; i++)
        #pragma unroll
        for (int j = 0; j < 2; j++)
            part[((size_t)s * BATCH + 4*by + i) * N + n0 + 2*cx + j] = acc[i][j];
}

// templated S -> fully unrolled partial reduction
template<int S, bool RELU>
__global__ void reduce_act_t(const float* __restrict__ part,
                             const float* __restrict__ bias,
                             float* __restrict__ out, int N)
{
    int idx = blockIdx.x * 256 + threadIdx.x;
    if (idx >= BATCH * N) return;
    int n = idx % N;
    float a = bias[n];
    #pragma unroll
    for (int s = 0; s < S; s++) a += part[(size_t)s * BATCH * N + idx];
    out[idx] = RELU ? fmaxf(a, 0.0f) : a;
}

// ---------------- group-conditioned mu/logvar heads (6144 warp dots) ----------------
__global__ void heads_kernel(const float* __restrict__ h2, const float* __restrict__ c,
                             const float* __restrict__ mu0w, const float* __restrict__ mu0b,
                             const float* __restrict__ lv0w, const float* __restrict__ lv0b,
                             const float* __restrict__ mu1w, const float* __restrict__ mu1b,
                             const float* __restrict__ lv1w, const float* __restrict__ lv1b,
                             float* __restrict__ mu, float* __restrict__ lv)
{
    int w = blockIdx.x * (blockDim.x >> 5) + (threadIdx.x >> 5);
    int lane = threadIdx.x & 31;
    if (w >= BATCH * 2 * NN) return;
    int b = w / (2 * NN);
    int r = w % (2 * NN);
    int which = r / NN;
    int n = r % NN;
    bool is0 = (c[b] == 0.0f);
    const float* wp = which == 0 ? (is0 ? mu0w : mu1w) : (is0 ? lv0w : lv1w);
    const float* bp = which == 0 ? (is0 ? mu0b : mu1b) : (is0 ? lv0b : lv1b);
    const float* hr = h2 + b * H1D;
    const float* wr = wp + n * H1D;
    float acc = 0.0f;
    #pragma unroll 4
    for (int k = lane; k < H1D; k += 32) acc = fmaf(hr[k], wr[k], acc);
    #pragma unroll
    for (int o = 16; o; o >>= 1) acc += __shfl_xor_sync(0xFFFFFFFFu, acc, o);
    if (lane == 0) (which ? lv : mu)[b * NN + n] = acc + bp[n];
}

// ---------------- fused reparam (inline eps) + z/log_q + y (one block per batch) ---------
__global__ void reparam_y_kernel(const float* __restrict__ mu, const float* __restrict__ lv,
                                 const float* __restrict__ c,
                                 const float* __restrict__ reg_w, const float* __restrict__ reg_b,
                                 float* __restrict__ z_scr, float* __restrict__ out)
{
    const int b = blockIdx.x;
    const int n = threadIdx.x;      // 96 threads
    const int lane = n & 31;
    __shared__ float zs[NN];

    float m = mu[b*NN + n], v = lv[b*NN + n];
    float e = tf_normal(b*NN + n);
    float sd = expf(0.5f * v);
    float z = fmaf(e, sd, m);
    zs[n] = z;
    z_scr[b*NN + n] = z;
    out[Z_OFF  + b*NN + n] = z;
    out[LQ_OFF + b*NN + n] = fmaf(-0.5f * e, e, -0.5f * v) - 0.91893853320467274f;
    __syncthreads();

    if (n < 32) {
        float s = 0.0f;
        #pragma unroll
        for (int l = lane; l < NN; l += 32) s = fmaf(zs[l], reg_w[l], s);
        #pragma unroll
        for (int o = 16; o; o >>= 1) s += __shfl_xor_sync(0xFFFFFFFFu, s, o);
        if (lane == 0) out[Y_OFF + b] = s + c[b] * reg_w[NN] + reg_b[0];
    }
}

// ---------------- fused decoder + graphconv (same 128-block grid) ------------------------
__global__ void dec_gc_kernel(const float* __restrict__ z, const float* __restrict__ c,
                              const float* __restrict__ dec_w, const float* __restrict__ dec_b,
                              const float* __restrict__ gc0w, const float* __restrict__ gc0b,
                              const float* __restrict__ gc1w, const float* __restrict__ gc1b,
                              float* __restrict__ g)
{
    int k = blockIdx.x, b = blockIdx.y, n = threadIdx.x;   // 96 threads
    __shared__ float zs[NN];
    __shared__ float ds[NN];
    zs[n] = z[b*NN + n];
    __syncthreads();

    // decoder
    {
        const float* wr = dec_w + (k*NN + n) * NN;
        float acc = dec_b[k*NN + n];
        #pragma unroll 8
        for (int l = 0; l < NN; l++) acc = fmaf(zs[l], wr[l], acc);
        ds[n] = 1.0f / (1.0f + expf(-acc));
    }
    __syncthreads();

    // graphconv (group-selected)
    bool is0 = (c[b] == 0.0f);
    const float* wr = (is0 ? gc0w : gc1w) + (k*NN + n) * NN;
    const float* bp = is0 ? gc0b : gc1b;
    float acc = bp[k*NN + n];
    #pragma unroll 8
    for (int l = 0; l < NN; l++) acc = fmaf(ds[l], wr[l], acc);
    g[(k*BATCH + b)*NN + n] = 1.0f / (1.0f + expf(-acc));
}

// ---------------- pre[b, i*96+j] = b_sel + sum_k W_sel[k] g[k,b,i] g[k,b,j] ----------------
__global__ void outer_kernel(const float* __restrict__ g, const float* __restrict__ c,
                             const float* __restrict__ W0, const float* __restrict__ b0v,
                             const float* __restrict__ W1, const float* __restrict__ b1v,
                             float* __restrict__ pre)
{
    int b = blockIdx.x, tid = threadIdx.x;
    __shared__ float gi[LDEC][NN];
    __shared__ float wg[LDEC][NN];
    bool is0 = (c[b] == 0.0f);
    const float* Wsel = is0 ? W0 : W1;
    const float* bsel = is0 ? b0v : b1v;
    for (int idx = tid; idx < LDEC * NN; idx += 256) {
        int k = idx / NN, n = idx % NN;
        float gv = g[(k*BATCH + b)*NN + n];
        gi[k][n] = gv;
        wg[k][n] = gv * Wsel[k];
    }
    __syncthreads();
    for (int idx = tid; idx < NSQ; idx += 256) {
        int i = idx / NN, j = idx % NN;
        float v = bsel[idx];
        #pragma unroll
        for (int k = 0; k < LDEC; k++) v = fmaf(wg[k][i], gi[k][j], v);
        pre[(size_t)b * NSQ + idx] = v;
    }
}

// ---------------- big fc GEMM: bf16 mma, cp.async W, split-K (R14-exact) ------------------
__device__ __forceinline__ unsigned pack_bf16(float lo, float hi) {
    unsigned r;
    asm("cvt.rn.bf16x2.f32 %0, %1, %2;" : "=r"(r) : "f"(hi), "f"(lo));
    return r;
}

__device__ __forceinline__ void cp16(void* smem_dst, const void* gsrc) {
    unsigned s = (unsigned)__cvta_generic_to_shared(smem_dst);
    asm volatile("cp.async.ca.shared.global [%0], [%1], 16;" :: "r"(s), "l"(gsrc));
}
#define CP_COMMIT() asm volatile("cp.async.commit_group;")
#define CP_WAIT(n)  asm volatile("cp.async.wait_group %0;" :: "n"(n))

#define MMA_BF16(d, a, b0, b1) \
    asm volatile("mma.sync.aligned.m16n8k16.row.col.f32.bf16.bf16.f32 " \
                 "{%0,%1,%2,%3}, {%4,%5,%6,%7}, {%8,%9}, {%0,%1,%2,%3};" \
                 : "+f"(d[0]), "+f"(d[1]), "+f"(d[2]), "+f"(d[3]) \
                 : "r"(a[0]), "r"(a[1]), "r"(a[2]), "r"(a[3]), "r"(b0), "r"(b1))

__global__ void __launch_bounds__(256, 1)
gemm_fc_mma(const float* __restrict__ A, const float* __restrict__ W,
            float* __restrict__ part)
{
    extern __shared__ float sm[];
    float*    WsBuf0 = sm;
    float*    WsBuf1 = sm + WSF_WORDS;
    unsigned* AsBuf0 = (unsigned*)(sm + 2*WSF_WORDS);
    unsigned* AsBuf1 = AsBuf0 + ASB_WORDS;

    const int tid  = threadIdx.x;
    const int lane = tid & 31;
    const int wid  = tid >> 5;
    const int q    = lane >> 2;
    const int s    = lane & 3;
    const int n0   = blockIdx.x * FCBN;
    const int kb   = blockIdx.y * FCKCH;

    float4 ast[2];
    float acc[2][4][4];
    #pragma unroll
    for (int rt = 0; rt < 2; rt++)
        #pragma unroll
        for (int j = 0; j < 4; j++)
            #pragma unroll
            for (int cc = 0; cc < 4; cc++) acc[rt][j][cc] = 0.0f;

    auto cp_w = [&](float* ws, int kt) {
        const float* wb = W + (size_t)kb + (size_t)kt * FCBK;
        #pragma unroll
        for (int it = 0; it < 16; it++) {
            int idx = it*256 + tid;
            int ci = idx >> 4, k4 = idx & 15;
            cp16(ws + ci * WS_F + 4*k4, wb + (size_t)(n0 + ci) * NSQ + 4*k4);
        }
    };
    auto lda = [&](int kt) {
        const float* ab = A + (size_t)lane * NSQ + kb + kt * FCBK;
        #pragma unroll
        for (int it = 0; it < 2; it++) ast[it] = *(const float4*)(ab + 4*(8*it + wid));
    };
    auto sta = [&](unsigned* as) {
        #pragma unroll
        for (int it = 0; it < 2; it++) {
            int k4 = 8*it + wid;
            as[lane * ASB_STRIDE + 2*k4]     = pack_bf16(ast[it].x, ast[it].y);
            as[lane * ASB_STRIDE + 2*k4 + 1] = pack_bf16(ast[it].z, ast[it].w);
        }
    };

    auto compute_tile = [&](const float* Wf, const unsigned* As) {
        #pragma unroll
        for (int k16 = 0; k16 < FCBK/16; k16++) {
            int koff = 8*k16;
            int ko   = 16*k16;
            unsigned a[2][4];
            #pragma unroll
            for (int rt = 0; rt < 2; rt++) {
                int r0 = q + 16*rt;
                a[rt][0] = As[r0 * ASB_STRIDE + s + koff];
                a[rt][1] = As[(r0 + 8) * ASB_STRIDE + s + koff];
                a[rt][2] = As[r0 * ASB_STRIDE + s + 4 + koff];
                a[rt][3] = As[(r0 + 8) * ASB_STRIDE + s + 4 + koff];
            }
            #pragma unroll
            for (int j = 0; j < 4; j++) {
                int ci = wid*32 + j*8 + q;
                const float* wp = Wf + ci * WS_F + ko;
                float2 w0 = *(const float2*)(wp + 2*s);
                float2 w1 = *(const float2*)(wp + 2*s + 8);
                unsigned b0 = pack_bf16(w0.x, w0.y);
                unsigned b1 = pack_bf16(w1.x, w1.y);
                MMA_BF16(acc[0][j], a[0], b0, b1);
                MMA_BF16(acc[1][j], a[1], b0, b1);
            }
        }
    };

    cp_w(WsBuf0, 0); CP_COMMIT();
    lda(0); sta(AsBuf0);
    cp_w(WsBuf1, 1); CP_COMMIT();
    lda(1);
    CP_WAIT(1);
    __syncthreads();

    for (int t = 0; t < FCTILES; t++) {
        const int p = t & 1;
        compute_tile(p ? WsBuf1 : WsBuf0, p ? AsBuf1 : AsBuf0);
        if (t + 1 < FCTILES) {
            sta(p ? AsBuf0 : AsBuf1);
            CP_WAIT(0);
            __syncthreads();
            if (t + 2 < FCTILES) {
                cp_w(p ? WsBuf1 : WsBuf0, t + 2);
                CP_COMMIT();
                lda(t + 2);
            }
        }
    }

    float* pbase = part + (size_t)blockIdx.y * BATCH * NSQ;
    #pragma unroll
    for (int rt = 0; rt < 2; rt++) {
        #pragma unroll
        for (int j = 0; j < 4; j++) {
            int row = q + 16*rt;
            int col = n0 + wid*32 + j*8 + 2*s;
            *(float2*)&pbase[(size_t)row * NSQ + col] =
                make_float2(acc[rt][j][0], acc[rt][j][1]);
            *(float2*)&pbase[(size_t)(row + 8) * NSQ + col] =
                make_float2(acc[rt][j][2], acc[rt][j][3]);
        }
    }
}

__global__ void fc_combine(const float* __restrict__ part, const float* __restrict__ bias,
                           float* __restrict__ xout)
{
    int idx = blockIdx.x * 256 + threadIdx.x;
    if (idx >= BATCH * NSQ) return;
    int n = idx % NSQ;
    float a = bias[n];
    #pragma unroll
    for (int s = 0; s < FCKS; s++) a += part[(size_t)s * BATCH * NSQ + idx];
    xout[idx] = expf(a);
}

// ---------------- launch ----------------
extern "C" void kernel_launch(void* const* d_in, const int* in_sizes, int n_in,
                              void* d_out, int out_size)
{
    const float* x_in   = (const float*)d_in[0];
    const float* c_in   = (const float*)d_in[1];
    const float* enc_w1 = (const float*)d_in[2];
    const float* enc_b1 = (const float*)d_in[3];
    const float* enc_w2 = (const float*)d_in[4];
    const float* enc_b2 = (const float*)d_in[5];
    const float* mu0_w  = (const float*)d_in[6];
    const float* mu0_b  = (const float*)d_in[7];
    const float* lv0_w  = (const float*)d_in[8];
    const float* lv0_b  = (const float*)d_in[9];
    const float* mu1_w  = (const float*)d_in[10];
    const float* mu1_b  = (const float*)d_in[11];
    const float* lv1_w  = (const float*)d_in[12];
    const float* lv1_b  = (const float*)d_in[13];
    const float* dec_w  = (const float*)d_in[14];
    const float* dec_b  = (const float*)d_in[15];
    const float* gc0_w  = (const float*)d_in[16];
    const float* gc0_b  = (const float*)d_in[17];
    const float* gc1_w  = (const float*)d_in[18];
    const float* gc1_b  = (const float*)d_in[19];
    const float* fc_w   = (const float*)d_in[20];
    const float* fc_b   = (const float*)d_in[21];
    const float* reg_w  = (const float*)d_in[22];
    const float* reg_b  = (const float*)d_in[23];
    const float* W0     = (const float*)d_in[24];
    const float* b0v    = (const float*)d_in[25];
    const float* W1     = (const float*)d_in[26];
    const float* b1v    = (const float*)d_in[27];
    float* out = (float*)d_out;

    void *p;
    float *part1, *h1, *part2, *h2, *mu, *lv, *z, *gbuf, *pre, *pfc;
    cudaGetSymbolAddress(&p, g_part1); part1 = (float*)p;
    cudaGetSymbolAddress(&p, g_h1);    h1    = (float*)p;
    cudaGetSymbolAddress(&p, g_part2); part2 = (float*)p;
    cudaGetSymbolAddress(&p, g_h2);    h2    = (float*)p;
    cudaGetSymbolAddress(&p, g_mu);    mu    = (float*)p;
    cudaGetSymbolAddress(&p, g_lv);    lv    = (float*)p;
    cudaGetSymbolAddress(&p, g_z);     z     = (float*)p;
    cudaGetSymbolAddress(&p, g_gg);    gbuf  = (float*)p;
    cudaGetSymbolAddress(&p, g_pre);   pre   = (float*)p;
    cudaGetSymbolAddress(&p, g_pfc);   pfc   = (float*)p;

    cudaFuncSetAttribute(gemm_fc_mma, cudaFuncAttributeMaxDynamicSharedMemorySize,
                         FC_SMEM_BYTES);

    // encoder
    gemm_tn_splitk<<<dim3(H2D/64, KS1), 256>>>(x_in, enc_w1, part1, H2D, NSQ, NSQ/KS1);
    reduce_act_t<KS1, true><<<(BATCH*H2D + 255)/256, 256>>>(part1, enc_b1, h1, H2D);
    gemm_tn_splitk<<<dim3(H1D/64, KS2), 256>>>(h1, enc_w2, part2, H1D, H2D, H2D/KS2);
    reduce_act_t<KS2, true><<<(BATCH*H1D + 255)/256, 256>>>(part2, enc_b2, h2, H1D);

    // heads (wide parallelism: 6144 warp dots)
    heads_kernel<<<768, 256>>>(h2, c_in, mu0_w, mu0_b, lv0_w, lv0_b,
                               mu1_w, mu1_b, lv1_w, lv1_b, mu, lv);

    // fused reparam + z/log_q + y
    reparam_y_kernel<<<BATCH, NN>>>(mu, lv, c_in, reg_w, reg_b, z, out);

    // fused decoder + graphconv (128 blocks)
    dec_gc_kernel<<<dim3(LDEC, BATCH), NN>>>(z, c_in, dec_w, dec_b,
                                             gc0_w, gc0_b, gc1_w, gc1_b, gbuf);
    outer_kernel<<<BATCH, 256>>>(gbuf, c_in, W0, b0v, W1, b1v, pre);

    // fc GEMM (bf16 tensor cores, cp.async W, split-K) + separate wide combine/exp
    gemm_fc_mma<<<dim3(NSQ/FCBN, FCKS), 256, FC_SMEM_BYTES>>>(pre, fc_w, pfc);
    fc_combine<<<(BATCH*NSQ + 255)/256, 256>>>(pfc, fc_b, out + X_OFF);
}